// round 13
// baseline (speedup 1.0000x reference)
#include <cuda_runtime.h>
#include <cuda_fp16.h>
#include <cstdint>

#define T_STEPS 48
#define B_SZ    512
#define D_SZ    1024
#define H_SZ    1024
#define G4      (4 * H_SZ)
#define BH      (B_SZ * H_SZ)

// ---------------- scratch (static device globals; no allocation) ----------
__device__ float    g_Gpool [B_SZ * G4];                          // 8 MB
__device__ float    g_Gin   [(size_t)(T_STEPS - 1) * B_SZ * G4];  // ~386 MB
__device__ float    g_bias_p[G4];
__device__ uint16_t g_wih_h [(size_t)G4 * 2 * D_SZ];              // 16 MB
__device__ uint16_t g_whh_h [(size_t)G4 * H_SZ];                  // 8 MB
__device__ uint16_t g_dh_h  [(size_t)(T_STEPS - 1) * B_SZ * D_SZ]; // 49 MB
__device__ uint16_t g_pl_h  [B_SZ * D_SZ];                        // 1 MB
__device__ uint16_t g_h_h   [2][BH];                              // ping-pong
__device__ unsigned int g_bar_ctr;                                // grid barrier

// ===================== helpers =============================================
__device__ __forceinline__ float sigf(float x) { return 1.f / (1.f + __expf(-x)); }
__device__ __forceinline__ float tanh_fast(float x) {
    float e = __expf(2.f * x);          // safe at +-inf
    return 1.f - 2.f / (e + 1.f);
}
__device__ __forceinline__ uint32_t smem_u32(const void* p) {
    uint32_t a;
    asm("{ .reg .u64 t; cvta.to.shared.u64 t, %1; cvt.u32.u64 %0, t; }"
        : "=r"(a) : "l"(p));
    return a;
}
__device__ __forceinline__ void cp16(uint32_t dst, const void* src) {
    asm volatile("cp.async.ca.shared.global [%0], [%1], 16;" :: "r"(dst), "l"(src));
}
#define CP_COMMIT() asm volatile("cp.async.commit_group;" ::: "memory")
#define CP_WAIT(n)  asm volatile("cp.async.wait_group %0;" :: "n"(n) : "memory")

__device__ __forceinline__ uint32_t fpack2(float f0, float f1) {
    uint32_t r;
    asm("cvt.rn.f16x2.f32 %0, %1, %2;" : "=r"(r) : "f"(f1), "f"(f0));
    return r;
}

// mma.sync m16n8k16 fp16: D += A*B (row.col), fp32 accumulate
#define MMA_F16(d, a, b)                                                      \
    asm volatile(                                                             \
        "mma.sync.aligned.m16n8k16.row.col.f32.f16.f16.f32 "                  \
        "{%0,%1,%2,%3}, {%4,%5,%6,%7}, {%8,%9}, {%0,%1,%2,%3};"               \
        : "+f"((d)[0]), "+f"((d)[1]), "+f"((d)[2]), "+f"((d)[3])              \
        : "r"((a)[0]), "r"((a)[1]), "r"((a)[2]), "r"((a)[3]),                 \
          "r"((b)[0]), "r"((b)[1]))

#define BK        32
#define ROW_BY    80                      // 64 B data + 16 pad, conflict-free
#define PLANE_BY  (128 * ROW_BY)          // 10240
#define STAGE_BY  (2 * PLANE_BY)          // Ah, Bh = 20480
#define NSTAGE    3
#define SMEM_B    (NSTAGE * STAGE_BY)     // 61440

// compute one k-iter (32 HMMA/warp) from stage buffer `st`
#define COMPUTE_KT(st)                                                        \
    do {                                                                      \
        const char* sAh = (st);                                               \
        const char* sBh = (st) + PLANE_BY;                                    \
        _Pragma("unroll")                                                     \
        for (int ks = 0; ks < 2; ks++) {                                      \
            const int kb = ks * 32 + t * 4;                                   \
            uint32_t bh[4][2];                                                \
            _Pragma("unroll")                                                 \
            for (int nt = 0; nt < 4; nt++) {                                  \
                const int rowb = (wn * 32 + nt * 8 + g) * ROW_BY + kb;        \
                bh[nt][0] = *(const uint32_t*)(sBh + rowb);                   \
                bh[nt][1] = *(const uint32_t*)(sBh + rowb + 16);              \
            }                                                                 \
            _Pragma("unroll")                                                 \
            for (int mt = 0; mt < 4; mt++) {                                  \
                const int rowb = (wm * 64 + mt * 16 + g) * ROW_BY + kb;       \
                uint32_t ah[4];                                               \
                ah[0] = *(const uint32_t*)(sAh + rowb);                       \
                ah[1] = *(const uint32_t*)(sAh + rowb + 8 * ROW_BY);          \
                ah[2] = *(const uint32_t*)(sAh + rowb + 16);                  \
                ah[3] = *(const uint32_t*)(sAh + rowb + 8 * ROW_BY + 16);     \
                _Pragma("unroll")                                             \
                for (int nt = 0; nt < 4; nt++) MMA_F16(acc[mt][nt], ah, bh[nt]); \
            }                                                                 \
        }                                                                     \
    } while (0)

// ===================== pure fp16 GEMM (parallel parts) ======================
// C[M,N] = f16(A)[M,K] @ f16(W)[N,K]^T + add + bias.
// 3-stage cp.async pipeline, ONE __syncthreads per k-iter.
__global__ __launch_bounds__(256, 2)
void gemm_f16(const uint16_t* __restrict__ Ah_, int lda,
              const uint16_t* __restrict__ Wh, int ldw,
              const float* __restrict__ add, int add_mod,
              const float* __restrict__ bias1,
              float* __restrict__ C, int N, int K)
{
    extern __shared__ char smc[];
    const uint32_t sb = smem_u32(smc);

    const int tid = threadIdx.x;
    const int wid = tid >> 5, lid = tid & 31;
    const int wm  = wid >> 2, wn = wid & 3;
    const int g   = lid >> 2, t  = lid & 3;
    const int m0  = blockIdx.y * 128;
    const int n0  = blockIdx.x * 128;

    float acc[4][4][4];
    #pragma unroll
    for (int a_ = 0; a_ < 4; a_++)
        #pragma unroll
        for (int b_ = 0; b_ < 4; b_++)
            #pragma unroll
            for (int e = 0; e < 4; e++) acc[a_][b_][e] = 0.f;

    const int r  = tid >> 1;
    const int jo = (tid & 1) * 32;
    const char* pAh = (const char*)(Ah_ + (size_t)(m0 + r) * lda) + jo;
    const char* pBh = (const char*)(Wh  + (size_t)(n0 + r) * ldw) + jo;
    const uint32_t dbase = sb + (uint32_t)(r * ROW_BY + jo);

    auto issue = [&](int kt, int s) {
        const size_t ko = (size_t)kt * (BK * 2);
        const uint32_t d0 = dbase + s * STAGE_BY;
        cp16(d0,            pAh + ko);  cp16(d0 + 16,            pAh + ko + 16);
        cp16(d0 + PLANE_BY, pBh + ko);  cp16(d0 + PLANE_BY + 16, pBh + ko + 16);
        CP_COMMIT();
    };

    const int KT = K / BK;
    issue(0, 0);
    issue(1, 1);

    for (int kt = 0; kt < KT; kt++) {
        if (kt + 1 < KT) CP_WAIT(1); else CP_WAIT(0);
        __syncthreads();
        if (kt + 2 < KT) issue(kt + 2, (kt + 2) % NSTAGE);
        COMPUTE_KT(smc + (kt % NSTAGE) * STAGE_BY);
    }

    #pragma unroll
    for (int mt = 0; mt < 4; mt++) {
        const int row  = m0 + wm * 64 + mt * 16 + g;
        const int row2 = row + 8;
        const int am   = add_mod ? (row  % add_mod) : row;
        const int am2  = add_mod ? (row2 % add_mod) : row2;
        #pragma unroll
        for (int nt = 0; nt < 4; nt++) {
            const int col = n0 + wn * 32 + nt * 8 + 2 * t;
            float v0 = acc[mt][nt][0], v1 = acc[mt][nt][1];
            float v2 = acc[mt][nt][2], v3 = acc[mt][nt][3];
            if (add) {
                v0 += add[(size_t)am  * N + col];
                v1 += add[(size_t)am  * N + col + 1];
                v2 += add[(size_t)am2 * N + col];
                v3 += add[(size_t)am2 * N + col + 1];
            }
            if (bias1) {
                v0 += bias1[col]; v1 += bias1[col + 1];
                v2 += bias1[col]; v3 += bias1[col + 1];
            }
            *(float2*)(C + (size_t)row  * N + col) = make_float2(v0, v1);
            *(float2*)(C + (size_t)row2 * N + col) = make_float2(v2, v3);
        }
    }
}

// ===================== persistent LSTM recurrence ============================
// 128 CTAs co-resident; grid barrier between steps; c in registers.
__global__ __launch_bounds__(256, 1)
void lstm_persist(const uint16_t* __restrict__ Whh,
                  const float* __restrict__ Gin,
                  uint16_t* __restrict__ h_base,    // [2][BH] ping-pong
                  float* __restrict__ outp)
{
    extern __shared__ char smc[];
    const uint32_t sb = smem_u32(smc);

    const int tid = threadIdx.x;
    const int wid = tid >> 5, lid = tid & 31;
    const int wm  = wid >> 2, wn = wid & 3;
    const int g   = lid >> 2, t  = lid & 3;
    const int m0  = (blockIdx.x & 3) * 128;
    const int n0  = (blockIdx.x >> 2) * 128;

    const int r  = tid >> 1;
    const int jo = (tid & 1) * 32;
    const char* pBh = (const char*)(Whh + (size_t)(n0 + r) * H_SZ) + jo;
    const uint32_t dbase = sb + (uint32_t)(r * ROW_BY + jo);

    float creg[4][4];
    #pragma unroll
    for (int mt = 0; mt < 4; mt++)
        #pragma unroll
        for (int nt = 0; nt < 4; nt++) creg[mt][nt] = 0.f;

    const bool even = ((t & 1) == 0);
    unsigned int bar_target = 0;

    for (int ts = 1; ts < T_STEPS; ts++) {
        float acc[4][4][4];
        #pragma unroll
        for (int a_ = 0; a_ < 4; a_++)
            #pragma unroll
            for (int b_ = 0; b_ < 4; b_++)
                #pragma unroll
                for (int e = 0; e < 4; e++) acc[a_][b_][e] = 0.f;

        if (ts >= 2) {
            const uint16_t* h_in = h_base + (size_t)((ts + 1) & 1) * BH;
            const char* pAh = (const char*)(h_in + (size_t)(m0 + r) * H_SZ) + jo;

            auto issue = [&](int kt, int s) {
                const size_t ko = (size_t)kt * (BK * 2);
                const uint32_t d0 = dbase + s * STAGE_BY;
                cp16(d0,            pAh + ko);  cp16(d0 + 16,            pAh + ko + 16);
                cp16(d0 + PLANE_BY, pBh + ko);  cp16(d0 + PLANE_BY + 16, pBh + ko + 16);
                CP_COMMIT();
            };

            const int KT = H_SZ / BK;   // 32
            issue(0, 0);
            issue(1, 1);

            for (int kt = 0; kt < KT; kt++) {
                if (kt + 1 < KT) CP_WAIT(1); else CP_WAIT(0);
                __syncthreads();
                if (kt + 2 < KT) issue(kt + 2, (kt + 2) % NSTAGE);
                COMPUTE_KT(smc + (kt % NSTAGE) * STAGE_BY);
            }
        }

        // ---- LSTM epilogue (gate-permuted cols jj*4+G) ----
        const float* add = Gin + (size_t)(ts - 1) * B_SZ * G4;
        uint16_t* h_out = h_base + (size_t)(ts & 1) * BH;
        #pragma unroll
        for (int mt = 0; mt < 4; mt++) {
            const int row  = m0 + wm * 64 + mt * 16 + g;
            const int row2 = row + 8;
            #pragma unroll
            for (int nt = 0; nt < 4; nt++) {
                const int col = n0 + wn * 32 + nt * 8 + 2 * t;
                float v0 = acc[mt][nt][0] + add[(size_t)row  * G4 + col];
                float v1 = acc[mt][nt][1] + add[(size_t)row  * G4 + col + 1];
                float v2 = acc[mt][nt][2] + add[(size_t)row2 * G4 + col];
                float v3 = acc[mt][nt][3] + add[(size_t)row2 * G4 + col + 1];
                float q0 = __shfl_xor_sync(0xffffffffu, v0, 1);
                float q1 = __shfl_xor_sync(0xffffffffu, v1, 1);
                float q2 = __shfl_xor_sync(0xffffffffu, v2, 1);
                float q3 = __shfl_xor_sync(0xffffffffu, v3, 1);
                float gi = even ? v0 : q2;
                float gf = even ? v1 : q3;
                float gg = even ? q0 : v2;
                float go = even ? q1 : v3;
                const int rr = even ? row : row2;
                const int jj = (n0 + wn * 32 + nt * 8 + ((t & 2) << 1)) >> 2;
                float si = sigf(gi), sf = sigf(gf), so = sigf(go);
                float tg = tanh_fast(gg);
                float cn = sf * creg[mt][nt] + si * tg;
                creg[mt][nt] = cn;
                float hn = so * tanh_fast(cn);
                h_out[(size_t)rr * H_SZ + jj] = (uint16_t)(fpack2(hn, 0.f) & 0xFFFFu);
                outp[(size_t)rr * T_STEPS * H_SZ + (size_t)ts * H_SZ + jj] = hn;
            }
        }

        // ---- grid barrier (h must be visible before next step) ----
        if (ts < T_STEPS - 1) {
            bar_target += gridDim.x;
            __syncthreads();
            if (tid == 0) {
                __threadfence();
                atomicAdd(&g_bar_ctr, 1u);
                unsigned int v;
                do {
                    asm volatile("ld.global.acquire.gpu.u32 %0, [%1];"
                                 : "=r"(v) : "l"(&g_bar_ctr));
                } while (v < bar_target);
            }
            __syncthreads();
        }
    }
}

// ---------------- prep kernels ----------------------------------------------
__global__ void permute_w_f16(const float* __restrict__ W,
                              uint16_t* __restrict__ Wh, int K)
{
    const int rr = blockIdx.x;
    const int jj = rr >> 2, G = rr & 3;
    const float4* s = (const float4*)(W + (size_t)(G * H_SZ + jj) * K);
    uint2* d = (uint2*)(Wh + (size_t)rr * K);
    for (int k = threadIdx.x; k < K / 4; k += blockDim.x) {
        float4 v = s[k];
        uint2 o;
        o.x = fpack2(v.x, v.y);
        o.y = fpack2(v.z, v.w);
        d[k] = o;
    }
}

__global__ void permute_bias(const float* __restrict__ b_ih,
                             const float* __restrict__ b_hh,
                             float* __restrict__ bp)
{
    int rr = blockIdx.x * blockDim.x + threadIdx.x;
    int jj = rr >> 2, G = rr & 3;
    bp[rr] = b_ih[G * H_SZ + jj] + b_hh[G * H_SZ + jj];
}

__global__ void conv_dh(const float* __restrict__ src, uint16_t* __restrict__ dst)
{
    size_t i = (size_t)blockIdx.x * blockDim.x + threadIdx.x;
    float4 v = ((const float4*)src)[i];
    uint2 o;
    o.x = fpack2(v.x, v.y);
    o.y = fpack2(v.z, v.w);
    ((uint2*)dst)[i] = o;
}

__global__ void pooled_kernel(const float* __restrict__ dh,
                              const int* __restrict__ cap,
                              uint16_t* __restrict__ ph)
{
    int b  = blockIdx.x;
    int d4 = threadIdx.x;
    float4 acc = make_float4(0.f, 0.f, 0.f, 0.f);
    float len = 0.f;
    #pragma unroll
    for (int t = 0; t < T_STEPS; t++) {
        int v = cap[t * B_SZ + b];
        float m = (v != 0 && v != 2) ? 1.f : 0.f;
        len += m;
        float4 x = *(const float4*)(dh + (size_t)t * B_SZ * D_SZ + (size_t)b * D_SZ + d4 * 4);
        acc.x += m * x.x; acc.y += m * x.y; acc.z += m * x.z; acc.w += m * x.w;
    }
    float inv = 1.f / len;
    uint2 o;
    o.x = fpack2(acc.x * inv, acc.y * inv);
    o.y = fpack2(acc.z * inv, acc.w * inv);
    ((uint2*)(ph + (size_t)b * D_SZ))[d4] = o;
}

// zero out[:,0,:]; reset grid-barrier counter
__global__ void init_kernel(float* __restrict__ out)
{
    int idx = blockIdx.x * blockDim.x + threadIdx.x;   // over B*H
    int b = idx >> 10;
    int j = idx & 1023;
    out[(size_t)b * T_STEPS * H_SZ + j] = 0.f;
    if (idx == 0) g_bar_ctr = 0u;
}

// ---------------------------------------------------------------------------
extern "C" void kernel_launch(void* const* d_in, const int* in_sizes, int n_in,
                              void* d_out, int out_size)
{
    const float* dh    = (const float*)d_in[0];      // [T,1,B,D] == [T,B,D]
    const int*   cap   = (const int*)d_in[2];        // [T,B] int32
    const float* W_ih  = (const float*)d_in[3];      // [4H, 2D]
    const float* W_hh  = (const float*)d_in[4];      // [4H, H]
    const float* b_ih  = (const float*)d_in[5];      // [4H]
    const float* b_hh  = (const float*)d_in[6];      // [4H]
    float*       out   = (float*)d_out;              // [B, T, H]

    float *Gpool, *Gin, *biasp;
    uint16_t *wih_h, *whh_h, *dh_h, *pl_h, *h_h;
    cudaGetSymbolAddress((void**)&Gpool, g_Gpool);
    cudaGetSymbolAddress((void**)&Gin,   g_Gin);
    cudaGetSymbolAddress((void**)&biasp, g_bias_p);
    cudaGetSymbolAddress((void**)&wih_h, g_wih_h);
    cudaGetSymbolAddress((void**)&whh_h, g_whh_h);
    cudaGetSymbolAddress((void**)&dh_h,  g_dh_h);
    cudaGetSymbolAddress((void**)&pl_h,  g_pl_h);
    cudaGetSymbolAddress((void**)&h_h,   g_h_h);

    cudaFuncSetAttribute(gemm_f16, cudaFuncAttributeMaxDynamicSharedMemorySize, SMEM_B);
    cudaFuncSetAttribute(lstm_persist, cudaFuncAttributeMaxDynamicSharedMemorySize, SMEM_B);

    // 0) prep: permute weights -> fp16, bias; convert dh[1:]; pooled mean
    permute_w_f16<<<G4, 256>>>(W_ih, wih_h, 2 * D_SZ);
    permute_w_f16<<<G4, 256>>>(W_hh, whh_h, H_SZ);
    permute_bias<<<G4 / 256, 256>>>(b_ih, b_hh, biasp);
    conv_dh<<<((T_STEPS - 1) * B_SZ * D_SZ / 4) / 256, 256>>>(
        dh + (size_t)B_SZ * D_SZ, dh_h);
    pooled_kernel<<<B_SZ, 256>>>(dh, cap, pl_h);
    init_kernel<<<(B_SZ * H_SZ) / 256, 256>>>(out);

    // 1) Gpool = pooled @ Wihp[:, D:]^T + bias_p
    gemm_f16<<<dim3(G4 / 128, B_SZ / 128), 256, SMEM_B>>>(
        pl_h, D_SZ, wih_h + D_SZ, 2 * D_SZ,
        nullptr, 0, biasp, Gpool, G4, D_SZ);

    // 2) Gin[t-1] = dh[t] @ Wihp[:, :D]^T + Gpool   (one big parallel GEMM)
    gemm_f16<<<dim3(G4 / 128, ((T_STEPS - 1) * B_SZ) / 128), 256, SMEM_B>>>(
        dh_h, D_SZ, wih_h, 2 * D_SZ,
        Gpool, B_SZ, nullptr, Gin, G4, D_SZ);

    // 3) entire recurrence in ONE persistent kernel (grid barrier between steps)
    lstm_persist<<<128, 256, SMEM_B>>>(whh_h, Gin, h_h, out);
}

// round 14
// speedup vs baseline: 1.1266x; 1.1266x over previous
#include <cuda_runtime.h>
#include <cuda_fp16.h>
#include <cstdint>

#define T_STEPS 48
#define B_SZ    512
#define D_SZ    1024
#define H_SZ    1024
#define G4      (4 * H_SZ)
#define BH      (B_SZ * H_SZ)

// ---------------- scratch (static device globals; no allocation) ----------
__device__ float    g_Gpool [B_SZ * G4];                          // 8 MB
__device__ float    g_Gin   [(size_t)(T_STEPS - 1) * B_SZ * G4];  // ~386 MB
__device__ float    g_bias_p[G4];
__device__ uint16_t g_wih_h [(size_t)G4 * 2 * D_SZ];              // 16 MB
__device__ uint16_t g_whh_h [(size_t)G4 * H_SZ];                  // 8 MB
__device__ uint16_t g_dh_h  [(size_t)(T_STEPS - 1) * B_SZ * D_SZ]; // 49 MB
__device__ uint16_t g_pl_h  [B_SZ * D_SZ];                        // 1 MB
__device__ uint16_t g_h_h   [2][BH];                              // ping-pong
__device__ unsigned int g_bar_ctr;                                // grid barrier

// ===================== helpers =============================================
__device__ __forceinline__ float sigf(float x) { return 1.f / (1.f + __expf(-x)); }
__device__ __forceinline__ float tanh_fast(float x) {
    float e = __expf(2.f * x);          // safe at +-inf
    return 1.f - 2.f / (e + 1.f);
}
__device__ __forceinline__ uint32_t smem_u32(const void* p) {
    uint32_t a;
    asm("{ .reg .u64 t; cvta.to.shared.u64 t, %1; cvt.u32.u64 %0, t; }"
        : "=r"(a) : "l"(p));
    return a;
}
__device__ __forceinline__ void cp16(uint32_t dst, const void* src) {
    asm volatile("cp.async.ca.shared.global [%0], [%1], 16;" :: "r"(dst), "l"(src));
}
#define CP_COMMIT() asm volatile("cp.async.commit_group;" ::: "memory")
#define CP_WAIT(n)  asm volatile("cp.async.wait_group %0;" :: "n"(n) : "memory")

__device__ __forceinline__ uint32_t fpack2(float f0, float f1) {
    uint32_t r;
    asm("cvt.rn.f16x2.f32 %0, %1, %2;" : "=r"(r) : "f"(f1), "f"(f0));
    return r;
}

// mma.sync m16n8k16 fp16: D += A*B (row.col), fp32 accumulate
#define MMA_F16(d, a, b)                                                      \
    asm volatile(                                                             \
        "mma.sync.aligned.m16n8k16.row.col.f32.f16.f16.f32 "                  \
        "{%0,%1,%2,%3}, {%4,%5,%6,%7}, {%8,%9}, {%0,%1,%2,%3};"               \
        : "+f"((d)[0]), "+f"((d)[1]), "+f"((d)[2]), "+f"((d)[3])              \
        : "r"((a)[0]), "r"((a)[1]), "r"((a)[2]), "r"((a)[3]),                 \
          "r"((b)[0]), "r"((b)[1]))

#define BK        32
#define ROW_BY    80                      // 64 B data + 16 pad, conflict-free
#define PLANE_BY  (128 * ROW_BY)          // 10240
#define STAGE_BY  (2 * PLANE_BY)          // Ah, Bh = 20480
#define SMEM_B    (2 * STAGE_BY)          // 40960 (2-stage, R12 measured-best)

// ===================== pure fp16 GEMM (parallel parts) ======================
// C[M,N] = f16(A)[M,K] @ f16(W)[N,K]^T + add + bias.  R12 config: 256 thr,
// 8 warps (2x4), warp tile 64x32, 2 CTA/SM, 2-stage cp.async.
__global__ __launch_bounds__(256, 2)
void gemm_f16(const uint16_t* __restrict__ Ah_, int lda,
              const uint16_t* __restrict__ Wh, int ldw,
              const float* __restrict__ add, int add_mod,
              const float* __restrict__ bias1,
              float* __restrict__ C, int N, int K)
{
    extern __shared__ char smc[];
    const uint32_t sb = smem_u32(smc);

    const int tid = threadIdx.x;
    const int wid = tid >> 5, lid = tid & 31;
    const int wm  = wid >> 2, wn = wid & 3;
    const int g   = lid >> 2, t  = lid & 3;
    const int m0  = blockIdx.y * 128;
    const int n0  = blockIdx.x * 128;

    float acc[4][4][4];
    #pragma unroll
    for (int a_ = 0; a_ < 4; a_++)
        #pragma unroll
        for (int b_ = 0; b_ < 4; b_++)
            #pragma unroll
            for (int e = 0; e < 4; e++) acc[a_][b_][e] = 0.f;

    const int r  = tid >> 1;
    const int jo = (tid & 1) * 32;
    const char* pAh = (const char*)(Ah_ + (size_t)(m0 + r) * lda) + jo;
    const char* pBh = (const char*)(Wh  + (size_t)(n0 + r) * ldw) + jo;
    const uint32_t dbase = sb + (uint32_t)(r * ROW_BY + jo);

    auto issue = [&](int kt, int s) {
        const size_t ko = (size_t)kt * (BK * 2);
        const uint32_t d0 = dbase + s * STAGE_BY;
        cp16(d0,            pAh + ko);  cp16(d0 + 16,            pAh + ko + 16);
        cp16(d0 + PLANE_BY, pBh + ko);  cp16(d0 + PLANE_BY + 16, pBh + ko + 16);
    };

    issue(0, 0); CP_COMMIT();

    const int KT = K / BK;
    for (int kt = 0; kt < KT; kt++) {
        if (kt + 1 < KT) { issue(kt + 1, (kt + 1) & 1); CP_COMMIT(); CP_WAIT(1); }
        else             { CP_WAIT(0); }
        __syncthreads();

        const char* st  = smc + (kt & 1) * STAGE_BY;
        const char* sAh = st;
        const char* sBh = st + PLANE_BY;

        #pragma unroll
        for (int ks = 0; ks < 2; ks++) {
            const int kb = ks * 32 + t * 4;
            uint32_t bh[4][2];
            #pragma unroll
            for (int nt = 0; nt < 4; nt++) {
                const int rowb = (wn * 32 + nt * 8 + g) * ROW_BY + kb;
                bh[nt][0] = *(const uint32_t*)(sBh + rowb);
                bh[nt][1] = *(const uint32_t*)(sBh + rowb + 16);
            }
            #pragma unroll
            for (int mt = 0; mt < 4; mt++) {
                const int rowb = (wm * 64 + mt * 16 + g) * ROW_BY + kb;
                uint32_t ah[4];
                ah[0] = *(const uint32_t*)(sAh + rowb);
                ah[1] = *(const uint32_t*)(sAh + rowb + 8 * ROW_BY);
                ah[2] = *(const uint32_t*)(sAh + rowb + 16);
                ah[3] = *(const uint32_t*)(sAh + rowb + 8 * ROW_BY + 16);
                #pragma unroll
                for (int nt = 0; nt < 4; nt++) MMA_F16(acc[mt][nt], ah, bh[nt]);
            }
        }
        __syncthreads();
    }

    #pragma unroll
    for (int mt = 0; mt < 4; mt++) {
        const int row  = m0 + wm * 64 + mt * 16 + g;
        const int row2 = row + 8;
        const int am   = add_mod ? (row  % add_mod) : row;
        const int am2  = add_mod ? (row2 % add_mod) : row2;
        #pragma unroll
        for (int nt = 0; nt < 4; nt++) {
            const int col = n0 + wn * 32 + nt * 8 + 2 * t;
            float v0 = acc[mt][nt][0], v1 = acc[mt][nt][1];
            float v2 = acc[mt][nt][2], v3 = acc[mt][nt][3];
            if (add) {
                v0 += add[(size_t)am  * N + col];
                v1 += add[(size_t)am  * N + col + 1];
                v2 += add[(size_t)am2 * N + col];
                v3 += add[(size_t)am2 * N + col + 1];
            }
            if (bias1) {
                v0 += bias1[col]; v1 += bias1[col + 1];
                v2 += bias1[col]; v3 += bias1[col + 1];
            }
            *(float2*)(C + (size_t)row  * N + col) = make_float2(v0, v1);
            *(float2*)(C + (size_t)row2 * N + col) = make_float2(v2, v3);
        }
    }
}

// ===================== persistent LSTM recurrence ============================
// 128 CTAs co-resident; grid barrier between steps; c in registers.
// 512 threads/CTA (16 warps/SM for issue-latency hiding), warp grid 4x4,
// warp tile 32x32.
__global__ __launch_bounds__(512, 1)
void lstm_persist(const uint16_t* __restrict__ Whh,
                  const float* __restrict__ Gin,
                  uint16_t* __restrict__ h_base,    // [2][BH] ping-pong
                  float* __restrict__ outp)
{
    extern __shared__ char smc[];
    const uint32_t sb = smem_u32(smc);

    const int tid = threadIdx.x;
    const int wid = tid >> 5, lid = tid & 31;
    const int wm  = wid >> 2, wn = wid & 3;        // 4x4 warp grid
    const int g   = lid >> 2, t  = lid & 3;
    const int m0  = (blockIdx.x & 3) * 128;
    const int n0  = (blockIdx.x >> 2) * 128;

    // loader: 512 threads; thread -> row r (0..127), 16-byte quarter jo
    const int r  = tid >> 2;
    const int jo = (tid & 3) * 16;
    const char* pBh = (const char*)(Whh + (size_t)(n0 + r) * H_SZ) + jo;
    const uint32_t dbase = sb + (uint32_t)(r * ROW_BY + jo);

    float creg[2][4];
    #pragma unroll
    for (int mt = 0; mt < 2; mt++)
        #pragma unroll
        for (int nt = 0; nt < 4; nt++) creg[mt][nt] = 0.f;

    const bool even = ((t & 1) == 0);
    unsigned int bar_target = 0;

    for (int ts = 1; ts < T_STEPS; ts++) {
        float acc[2][4][4];
        #pragma unroll
        for (int a_ = 0; a_ < 2; a_++)
            #pragma unroll
            for (int b_ = 0; b_ < 4; b_++)
                #pragma unroll
                for (int e = 0; e < 4; e++) acc[a_][b_][e] = 0.f;

        if (ts >= 2) {
            const uint16_t* h_in = h_base + (size_t)((ts + 1) & 1) * BH;
            const char* pAh = (const char*)(h_in + (size_t)(m0 + r) * H_SZ) + jo;

            auto issue = [&](int kt, int s) {
                const size_t ko = (size_t)kt * (BK * 2);
                const uint32_t d0 = dbase + s * STAGE_BY;
                cp16(d0,            pAh + ko);
                cp16(d0 + PLANE_BY, pBh + ko);
            };

            issue(0, 0); CP_COMMIT();

            const int KT = H_SZ / BK;   // 32
            for (int kt = 0; kt < KT; kt++) {
                if (kt + 1 < KT) { issue(kt + 1, (kt + 1) & 1); CP_COMMIT(); CP_WAIT(1); }
                else             { CP_WAIT(0); }
                __syncthreads();

                const char* st  = smc + (kt & 1) * STAGE_BY;
                const char* sAh = st;
                const char* sBh = st + PLANE_BY;

                #pragma unroll
                for (int ks = 0; ks < 2; ks++) {
                    const int kb = ks * 32 + t * 4;
                    uint32_t bh[4][2];
                    #pragma unroll
                    for (int nt = 0; nt < 4; nt++) {
                        const int rowb = (wn * 32 + nt * 8 + g) * ROW_BY + kb;
                        bh[nt][0] = *(const uint32_t*)(sBh + rowb);
                        bh[nt][1] = *(const uint32_t*)(sBh + rowb + 16);
                    }
                    #pragma unroll
                    for (int mt = 0; mt < 2; mt++) {
                        const int rowb = (wm * 32 + mt * 16 + g) * ROW_BY + kb;
                        uint32_t ah[4];
                        ah[0] = *(const uint32_t*)(sAh + rowb);
                        ah[1] = *(const uint32_t*)(sAh + rowb + 8 * ROW_BY);
                        ah[2] = *(const uint32_t*)(sAh + rowb + 16);
                        ah[3] = *(const uint32_t*)(sAh + rowb + 8 * ROW_BY + 16);
                        #pragma unroll
                        for (int nt = 0; nt < 4; nt++) MMA_F16(acc[mt][nt], ah, bh[nt]);
                    }
                }
                __syncthreads();
            }
        }

        // ---- LSTM epilogue (gate-permuted cols jj*4+G) ----
        const float* add = Gin + (size_t)(ts - 1) * B_SZ * G4;
        uint16_t* h_out = h_base + (size_t)(ts & 1) * BH;
        #pragma unroll
        for (int mt = 0; mt < 2; mt++) {
            const int row  = m0 + wm * 32 + mt * 16 + g;
            const int row2 = row + 8;
            #pragma unroll
            for (int nt = 0; nt < 4; nt++) {
                const int col = n0 + wn * 32 + nt * 8 + 2 * t;
                float v0 = acc[mt][nt][0] + add[(size_t)row  * G4 + col];
                float v1 = acc[mt][nt][1] + add[(size_t)row  * G4 + col + 1];
                float v2 = acc[mt][nt][2] + add[(size_t)row2 * G4 + col];
                float v3 = acc[mt][nt][3] + add[(size_t)row2 * G4 + col + 1];
                float q0 = __shfl_xor_sync(0xffffffffu, v0, 1);
                float q1 = __shfl_xor_sync(0xffffffffu, v1, 1);
                float q2 = __shfl_xor_sync(0xffffffffu, v2, 1);
                float q3 = __shfl_xor_sync(0xffffffffu, v3, 1);
                float gi = even ? v0 : q2;
                float gf = even ? v1 : q3;
                float gg = even ? q0 : v2;
                float go = even ? q1 : v3;
                const int rr = even ? row : row2;
                const int jj = (n0 + wn * 32 + nt * 8 + ((t & 2) << 1)) >> 2;
                float si = sigf(gi), sf = sigf(gf), so = sigf(go);
                float tg = tanh_fast(gg);
                float cn = sf * creg[mt][nt] + si * tg;
                creg[mt][nt] = cn;
                float hn = so * tanh_fast(cn);
                h_out[(size_t)rr * H_SZ + jj] = (uint16_t)(fpack2(hn, 0.f) & 0xFFFFu);
                outp[(size_t)rr * T_STEPS * H_SZ + (size_t)ts * H_SZ + jj] = hn;
            }
        }

        // ---- grid barrier (h must be visible before next step) ----
        if (ts < T_STEPS - 1) {
            bar_target += gridDim.x;
            __syncthreads();
            if (tid == 0) {
                __threadfence();
                atomicAdd(&g_bar_ctr, 1u);
                unsigned int v;
                do {
                    asm volatile("ld.global.acquire.gpu.u32 %0, [%1];"
                                 : "=r"(v) : "l"(&g_bar_ctr));
                } while (v < bar_target);
            }
            __syncthreads();
        }
    }
}

// ---------------- prep kernels ----------------------------------------------
__global__ void permute_w_f16(const float* __restrict__ W,
                              uint16_t* __restrict__ Wh, int K)
{
    const int rr = blockIdx.x;
    const int jj = rr >> 2, G = rr & 3;
    const float4* s = (const float4*)(W + (size_t)(G * H_SZ + jj) * K);
    uint2* d = (uint2*)(Wh + (size_t)rr * K);
    for (int k = threadIdx.x; k < K / 4; k += blockDim.x) {
        float4 v = s[k];
        uint2 o;
        o.x = fpack2(v.x, v.y);
        o.y = fpack2(v.z, v.w);
        d[k] = o;
    }
}

__global__ void permute_bias(const float* __restrict__ b_ih,
                             const float* __restrict__ b_hh,
                             float* __restrict__ bp)
{
    int rr = blockIdx.x * blockDim.x + threadIdx.x;
    int jj = rr >> 2, G = rr & 3;
    bp[rr] = b_ih[G * H_SZ + jj] + b_hh[G * H_SZ + jj];
}

__global__ void conv_dh(const float* __restrict__ src, uint16_t* __restrict__ dst)
{
    size_t i = (size_t)blockIdx.x * blockDim.x + threadIdx.x;
    float4 v = ((const float4*)src)[i];
    uint2 o;
    o.x = fpack2(v.x, v.y);
    o.y = fpack2(v.z, v.w);
    ((uint2*)dst)[i] = o;
}

__global__ void pooled_kernel(const float* __restrict__ dh,
                              const int* __restrict__ cap,
                              uint16_t* __restrict__ ph)
{
    int b  = blockIdx.x;
    int d4 = threadIdx.x;
    float4 acc = make_float4(0.f, 0.f, 0.f, 0.f);
    float len = 0.f;
    #pragma unroll
    for (int t = 0; t < T_STEPS; t++) {
        int v = cap[t * B_SZ + b];
        float m = (v != 0 && v != 2) ? 1.f : 0.f;
        len += m;
        float4 x = *(const float4*)(dh + (size_t)t * B_SZ * D_SZ + (size_t)b * D_SZ + d4 * 4);
        acc.x += m * x.x; acc.y += m * x.y; acc.z += m * x.z; acc.w += m * x.w;
    }
    float inv = 1.f / len;
    uint2 o;
    o.x = fpack2(acc.x * inv, acc.y * inv);
    o.y = fpack2(acc.z * inv, acc.w * inv);
    ((uint2*)(ph + (size_t)b * D_SZ))[d4] = o;
}

// zero out[:,0,:]; reset grid-barrier counter
__global__ void init_kernel(float* __restrict__ out)
{
    int idx = blockIdx.x * blockDim.x + threadIdx.x;   // over B*H
    int b = idx >> 10;
    int j = idx & 1023;
    out[(size_t)b * T_STEPS * H_SZ + j] = 0.f;
    if (idx == 0) g_bar_ctr = 0u;
}

// ---------------------------------------------------------------------------
extern "C" void kernel_launch(void* const* d_in, const int* in_sizes, int n_in,
                              void* d_out, int out_size)
{
    const float* dh    = (const float*)d_in[0];      // [T,1,B,D] == [T,B,D]
    const int*   cap   = (const int*)d_in[2];        // [T,B] int32
    const float* W_ih  = (const float*)d_in[3];      // [4H, 2D]
    const float* W_hh  = (const float*)d_in[4];      // [4H, H]
    const float* b_ih  = (const float*)d_in[5];      // [4H]
    const float* b_hh  = (const float*)d_in[6];      // [4H]
    float*       out   = (float*)d_out;              // [B, T, H]

    float *Gpool, *Gin, *biasp;
    uint16_t *wih_h, *whh_h, *dh_h, *pl_h, *h_h;
    cudaGetSymbolAddress((void**)&Gpool, g_Gpool);
    cudaGetSymbolAddress((void**)&Gin,   g_Gin);
    cudaGetSymbolAddress((void**)&biasp, g_bias_p);
    cudaGetSymbolAddress((void**)&wih_h, g_wih_h);
    cudaGetSymbolAddress((void**)&whh_h, g_whh_h);
    cudaGetSymbolAddress((void**)&dh_h,  g_dh_h);
    cudaGetSymbolAddress((void**)&pl_h,  g_pl_h);
    cudaGetSymbolAddress((void**)&h_h,   g_h_h);

    cudaFuncSetAttribute(gemm_f16, cudaFuncAttributeMaxDynamicSharedMemorySize, SMEM_B);
    cudaFuncSetAttribute(lstm_persist, cudaFuncAttributeMaxDynamicSharedMemorySize, SMEM_B);

    // 0) prep: permute weights -> fp16, bias; convert dh[1:]; pooled mean
    permute_w_f16<<<G4, 256>>>(W_ih, wih_h, 2 * D_SZ);
    permute_w_f16<<<G4, 256>>>(W_hh, whh_h, H_SZ);
    permute_bias<<<G4 / 256, 256>>>(b_ih, b_hh, biasp);
    conv_dh<<<((T_STEPS - 1) * B_SZ * D_SZ / 4) / 256, 256>>>(
        dh + (size_t)B_SZ * D_SZ, dh_h);
    pooled_kernel<<<B_SZ, 256>>>(dh, cap, pl_h);
    init_kernel<<<(B_SZ * H_SZ) / 256, 256>>>(out);

    // 1) Gpool = pooled @ Wihp[:, D:]^T + bias_p
    gemm_f16<<<dim3(G4 / 128, B_SZ / 128), 256, SMEM_B>>>(
        pl_h, D_SZ, wih_h + D_SZ, 2 * D_SZ,
        nullptr, 0, biasp, Gpool, G4, D_SZ);

    // 2) Gin[t-1] = dh[t] @ Wihp[:, :D]^T + Gpool   (one big parallel GEMM)
    gemm_f16<<<dim3(G4 / 128, ((T_STEPS - 1) * B_SZ) / 128), 256, SMEM_B>>>(
        dh_h, D_SZ, wih_h, 2 * D_SZ,
        Gpool, B_SZ, nullptr, Gin, G4, D_SZ);

    // 3) entire recurrence in ONE persistent kernel (grid barrier between steps)
    lstm_persist<<<128, 512, SMEM_B>>>(whh_h, Gin, h_h, out);
}

// round 15
// speedup vs baseline: 1.1537x; 1.0241x over previous
#include <cuda_runtime.h>
#include <cuda_fp16.h>
#include <cstdint>

#define T_STEPS 48
#define B_SZ    512
#define D_SZ    1024
#define H_SZ    1024
#define G4      (4 * H_SZ)
#define BH      (B_SZ * H_SZ)

// ---------------- scratch (static device globals; no allocation) ----------
__device__ float    g_Gpool [B_SZ * G4];                          // 8 MB
__device__ float    g_Gin   [(size_t)(T_STEPS - 1) * B_SZ * G4];  // ~386 MB
__device__ float    g_bias_p[G4];
__device__ uint16_t g_wih_h [(size_t)G4 * 2 * D_SZ];              // 16 MB
__device__ uint16_t g_whh_h [(size_t)G4 * H_SZ];                  // 8 MB
__device__ uint16_t g_dh_h  [(size_t)(T_STEPS - 1) * B_SZ * D_SZ]; // 49 MB
__device__ uint16_t g_pl_h  [B_SZ * D_SZ];                        // 1 MB
__device__ uint16_t g_h_h   [2][BH];                              // ping-pong
__device__ unsigned int g_bar_ctr;                                // grid barrier

// ===================== helpers =============================================
// 1-MUFU activations (tanh.approx.f32, sm_75+)
__device__ __forceinline__ float tanha(float x) {
    float y; asm("tanh.approx.f32 %0, %1;" : "=f"(y) : "f"(x)); return y;
}
__device__ __forceinline__ float siga(float x) {
    return fmaf(tanha(0.5f * x), 0.5f, 0.5f);
}
__device__ __forceinline__ uint32_t smem_u32(const void* p) {
    uint32_t a;
    asm("{ .reg .u64 t; cvta.to.shared.u64 t, %1; cvt.u32.u64 %0, t; }"
        : "=r"(a) : "l"(p));
    return a;
}
__device__ __forceinline__ void cp16(uint32_t dst, const void* src) {
    asm volatile("cp.async.ca.shared.global [%0], [%1], 16;" :: "r"(dst), "l"(src));
}
#define CP_COMMIT() asm volatile("cp.async.commit_group;" ::: "memory")
#define CP_WAIT(n)  asm volatile("cp.async.wait_group %0;" :: "n"(n) : "memory")

__device__ __forceinline__ uint32_t fpack2(float f0, float f1) {
    uint32_t r;
    asm("cvt.rn.f16x2.f32 %0, %1, %2;" : "=r"(r) : "f"(f1), "f"(f0));
    return r;
}

// mma.sync m16n8k16 fp16: D += A*B (row.col), fp32 accumulate
#define MMA_F16(d, a, b)                                                      \
    asm volatile(                                                             \
        "mma.sync.aligned.m16n8k16.row.col.f32.f16.f16.f32 "                  \
        "{%0,%1,%2,%3}, {%4,%5,%6,%7}, {%8,%9}, {%0,%1,%2,%3};"               \
        : "+f"((d)[0]), "+f"((d)[1]), "+f"((d)[2]), "+f"((d)[3])              \
        : "r"((a)[0]), "r"((a)[1]), "r"((a)[2]), "r"((a)[3]),                 \
          "r"((b)[0]), "r"((b)[1]))

#define BK        32
#define ROW_BY    80                      // 64 B data + 16 pad, conflict-free
#define PLANE_BY  (128 * ROW_BY)          // 10240
#define STAGE_BY  (2 * PLANE_BY)          // Ah, Bh = 20480
#define SMEM_B    (2 * STAGE_BY)          // 40960 (2-stage, measured-best)

// ===================== pure fp16 GEMM (parallel parts) ======================
// C[M,N] = f16(A)[M,K] @ f16(W)[N,K]^T + add + bias.  R12 config: 256 thr,
// 8 warps (2x4), warp tile 64x32, 2 CTA/SM, 2-stage cp.async.
__global__ __launch_bounds__(256, 2)
void gemm_f16(const uint16_t* __restrict__ Ah_, int lda,
              const uint16_t* __restrict__ Wh, int ldw,
              const float* __restrict__ add, int add_mod,
              const float* __restrict__ bias1,
              float* __restrict__ C, int N, int K)
{
    extern __shared__ char smc[];
    const uint32_t sb = smem_u32(smc);

    const int tid = threadIdx.x;
    const int wid = tid >> 5, lid = tid & 31;
    const int wm  = wid >> 2, wn = wid & 3;
    const int g   = lid >> 2, t  = lid & 3;
    const int m0  = blockIdx.y * 128;
    const int n0  = blockIdx.x * 128;

    float acc[4][4][4];
    #pragma unroll
    for (int a_ = 0; a_ < 4; a_++)
        #pragma unroll
        for (int b_ = 0; b_ < 4; b_++)
            #pragma unroll
            for (int e = 0; e < 4; e++) acc[a_][b_][e] = 0.f;

    const int r  = tid >> 1;
    const int jo = (tid & 1) * 32;
    const char* pAh = (const char*)(Ah_ + (size_t)(m0 + r) * lda) + jo;
    const char* pBh = (const char*)(Wh  + (size_t)(n0 + r) * ldw) + jo;
    const uint32_t dbase = sb + (uint32_t)(r * ROW_BY + jo);

    auto issue = [&](int kt, int s) {
        const size_t ko = (size_t)kt * (BK * 2);
        const uint32_t d0 = dbase + s * STAGE_BY;
        cp16(d0,            pAh + ko);  cp16(d0 + 16,            pAh + ko + 16);
        cp16(d0 + PLANE_BY, pBh + ko);  cp16(d0 + PLANE_BY + 16, pBh + ko + 16);
    };

    issue(0, 0); CP_COMMIT();

    const int KT = K / BK;
    for (int kt = 0; kt < KT; kt++) {
        if (kt + 1 < KT) { issue(kt + 1, (kt + 1) & 1); CP_COMMIT(); CP_WAIT(1); }
        else             { CP_WAIT(0); }
        __syncthreads();

        const char* st  = smc + (kt & 1) * STAGE_BY;
        const char* sAh = st;
        const char* sBh = st + PLANE_BY;

        #pragma unroll
        for (int ks = 0; ks < 2; ks++) {
            const int kb = ks * 32 + t * 4;
            uint32_t bh[4][2];
            #pragma unroll
            for (int nt = 0; nt < 4; nt++) {
                const int rowb = (wn * 32 + nt * 8 + g) * ROW_BY + kb;
                bh[nt][0] = *(const uint32_t*)(sBh + rowb);
                bh[nt][1] = *(const uint32_t*)(sBh + rowb + 16);
            }
            #pragma unroll
            for (int mt = 0; mt < 4; mt++) {
                const int rowb = (wm * 64 + mt * 16 + g) * ROW_BY + kb;
                uint32_t ah[4];
                ah[0] = *(const uint32_t*)(sAh + rowb);
                ah[1] = *(const uint32_t*)(sAh + rowb + 8 * ROW_BY);
                ah[2] = *(const uint32_t*)(sAh + rowb + 16);
                ah[3] = *(const uint32_t*)(sAh + rowb + 8 * ROW_BY + 16);
                #pragma unroll
                for (int nt = 0; nt < 4; nt++) MMA_F16(acc[mt][nt], ah, bh[nt]);
            }
        }
        __syncthreads();
    }

    #pragma unroll
    for (int mt = 0; mt < 4; mt++) {
        const int row  = m0 + wm * 64 + mt * 16 + g;
        const int row2 = row + 8;
        const int am   = add_mod ? (row  % add_mod) : row;
        const int am2  = add_mod ? (row2 % add_mod) : row2;
        #pragma unroll
        for (int nt = 0; nt < 4; nt++) {
            const int col = n0 + wn * 32 + nt * 8 + 2 * t;
            float v0 = acc[mt][nt][0], v1 = acc[mt][nt][1];
            float v2 = acc[mt][nt][2], v3 = acc[mt][nt][3];
            if (add) {
                float2 a0 = *(const float2*)(add + (size_t)am  * N + col);
                float2 a1 = *(const float2*)(add + (size_t)am2 * N + col);
                v0 += a0.x; v1 += a0.y; v2 += a1.x; v3 += a1.y;
            }
            if (bias1) {
                v0 += bias1[col]; v1 += bias1[col + 1];
                v2 += bias1[col]; v3 += bias1[col + 1];
            }
            *(float2*)(C + (size_t)row  * N + col) = make_float2(v0, v1);
            *(float2*)(C + (size_t)row2 * N + col) = make_float2(v2, v3);
        }
    }
}

// ===================== persistent LSTM recurrence ============================
// 128 CTAs co-resident; grid barrier between steps; c in registers.
// 512 threads/CTA (16 warps/SM), warp grid 4x4, warp tile 32x32.
// Activations via tanh.approx (1 MUFU each): 5 MUFU/cell vs 10 with expf.
__global__ __launch_bounds__(512, 1)
void lstm_persist(const uint16_t* __restrict__ Whh,
                  const float* __restrict__ Gin,
                  uint16_t* __restrict__ h_base,    // [2][BH] ping-pong
                  float* __restrict__ outp)
{
    extern __shared__ char smc[];
    const uint32_t sb = smem_u32(smc);

    const int tid = threadIdx.x;
    const int wid = tid >> 5, lid = tid & 31;
    const int wm  = wid >> 2, wn = wid & 3;        // 4x4 warp grid
    const int g   = lid >> 2, t  = lid & 3;
    const int m0  = (blockIdx.x & 3) * 128;
    const int n0  = (blockIdx.x >> 2) * 128;

    // loader: 512 threads; thread -> row r (0..127), 16-byte quarter jo
    const int r  = tid >> 2;
    const int jo = (tid & 3) * 16;
    const char* pBh = (const char*)(Whh + (size_t)(n0 + r) * H_SZ) + jo;
    const uint32_t dbase = sb + (uint32_t)(r * ROW_BY + jo);

    float creg[2][4];
    #pragma unroll
    for (int mt = 0; mt < 2; mt++)
        #pragma unroll
        for (int nt = 0; nt < 4; nt++) creg[mt][nt] = 0.f;

    const bool even = ((t & 1) == 0);
    unsigned int bar_target = 0;

    for (int ts = 1; ts < T_STEPS; ts++) {
        float acc[2][4][4];
        #pragma unroll
        for (int a_ = 0; a_ < 2; a_++)
            #pragma unroll
            for (int b_ = 0; b_ < 4; b_++)
                #pragma unroll
                for (int e = 0; e < 4; e++) acc[a_][b_][e] = 0.f;

        if (ts >= 2) {
            const uint16_t* h_in = h_base + (size_t)((ts + 1) & 1) * BH;
            const char* pAh = (const char*)(h_in + (size_t)(m0 + r) * H_SZ) + jo;

            auto issue = [&](int kt, int s) {
                const size_t ko = (size_t)kt * (BK * 2);
                const uint32_t d0 = dbase + s * STAGE_BY;
                cp16(d0,            pAh + ko);
                cp16(d0 + PLANE_BY, pBh + ko);
            };

            issue(0, 0); CP_COMMIT();

            const int KT = H_SZ / BK;   // 32
            for (int kt = 0; kt < KT; kt++) {
                if (kt + 1 < KT) { issue(kt + 1, (kt + 1) & 1); CP_COMMIT(); CP_WAIT(1); }
                else             { CP_WAIT(0); }
                __syncthreads();

                const char* st  = smc + (kt & 1) * STAGE_BY;
                const char* sAh = st;
                const char* sBh = st + PLANE_BY;

                #pragma unroll
                for (int ks = 0; ks < 2; ks++) {
                    const int kb = ks * 32 + t * 4;
                    uint32_t bh[4][2];
                    #pragma unroll
                    for (int nt = 0; nt < 4; nt++) {
                        const int rowb = (wn * 32 + nt * 8 + g) * ROW_BY + kb;
                        bh[nt][0] = *(const uint32_t*)(sBh + rowb);
                        bh[nt][1] = *(const uint32_t*)(sBh + rowb + 16);
                    }
                    #pragma unroll
                    for (int mt = 0; mt < 2; mt++) {
                        const int rowb = (wm * 32 + mt * 16 + g) * ROW_BY + kb;
                        uint32_t ah[4];
                        ah[0] = *(const uint32_t*)(sAh + rowb);
                        ah[1] = *(const uint32_t*)(sAh + rowb + 8 * ROW_BY);
                        ah[2] = *(const uint32_t*)(sAh + rowb + 16);
                        ah[3] = *(const uint32_t*)(sAh + rowb + 8 * ROW_BY + 16);
                        #pragma unroll
                        for (int nt = 0; nt < 4; nt++) MMA_F16(acc[mt][nt], ah, bh[nt]);
                    }
                }
                __syncthreads();
            }
        }

        // ---- LSTM epilogue (gate-permuted cols jj*4+G; 5 MUFU/cell) ----
        const float* add = Gin + (size_t)(ts - 1) * B_SZ * G4;
        uint16_t* h_out = h_base + (size_t)(ts & 1) * BH;
        #pragma unroll
        for (int mt = 0; mt < 2; mt++) {
            const int row  = m0 + wm * 32 + mt * 16 + g;
            const int row2 = row + 8;
            #pragma unroll
            for (int nt = 0; nt < 4; nt++) {
                const int col = n0 + wn * 32 + nt * 8 + 2 * t;
                float2 a0 = *(const float2*)(add + (size_t)row  * G4 + col);
                float2 a1 = *(const float2*)(add + (size_t)row2 * G4 + col);
                float v0 = acc[mt][nt][0] + a0.x;
                float v1 = acc[mt][nt][1] + a0.y;
                float v2 = acc[mt][nt][2] + a1.x;
                float v3 = acc[mt][nt][3] + a1.y;
                float q0 = __shfl_xor_sync(0xffffffffu, v0, 1);
                float q1 = __shfl_xor_sync(0xffffffffu, v1, 1);
                float q2 = __shfl_xor_sync(0xffffffffu, v2, 1);
                float q3 = __shfl_xor_sync(0xffffffffu, v3, 1);
                float gi = even ? v0 : q2;
                float gf = even ? v1 : q3;
                float gg = even ? q0 : v2;
                float go = even ? q1 : v3;
                const int rr = even ? row : row2;
                const int jj = (n0 + wn * 32 + nt * 8 + ((t & 2) << 1)) >> 2;
                float si = siga(gi), sf = siga(gf), so = siga(go);
                float tg = tanha(gg);
                float cn = sf * creg[mt][nt] + si * tg;
                creg[mt][nt] = cn;
                float hn = so * tanha(cn);
                h_out[(size_t)rr * H_SZ + jj] = (uint16_t)(fpack2(hn, 0.f) & 0xFFFFu);
                outp[(size_t)rr * T_STEPS * H_SZ + (size_t)ts * H_SZ + jj] = hn;
            }
        }

        // ---- grid barrier (h must be visible before next step) ----
        if (ts < T_STEPS - 1) {
            bar_target += gridDim.x;
            __syncthreads();
            if (tid == 0) {
                __threadfence();
                atomicAdd(&g_bar_ctr, 1u);
                unsigned int v;
                do {
                    asm volatile("ld.global.acquire.gpu.u32 %0, [%1];"
                                 : "=r"(v) : "l"(&g_bar_ctr));
                } while (v < bar_target);
            }
            __syncthreads();
        }
    }
}

// ---------------- prep kernels ----------------------------------------------
__global__ void permute_w_f16(const float* __restrict__ W,
                              uint16_t* __restrict__ Wh, int K)
{
    const int rr = blockIdx.x;
    const int jj = rr >> 2, G = rr & 3;
    const float4* s = (const float4*)(W + (size_t)(G * H_SZ + jj) * K);
    uint2* d = (uint2*)(Wh + (size_t)rr * K);
    for (int k = threadIdx.x; k < K / 4; k += blockDim.x) {
        float4 v = s[k];
        uint2 o;
        o.x = fpack2(v.x, v.y);
        o.y = fpack2(v.z, v.w);
        d[k] = o;
    }
}

__global__ void permute_bias(const float* __restrict__ b_ih,
                             const float* __restrict__ b_hh,
                             float* __restrict__ bp)
{
    int rr = blockIdx.x * blockDim.x + threadIdx.x;
    int jj = rr >> 2, G = rr & 3;
    bp[rr] = b_ih[G * H_SZ + jj] + b_hh[G * H_SZ + jj];
}

__global__ void conv_dh(const float* __restrict__ src, uint16_t* __restrict__ dst)
{
    size_t i = (size_t)blockIdx.x * blockDim.x + threadIdx.x;
    float4 v = ((const float4*)src)[i];
    uint2 o;
    o.x = fpack2(v.x, v.y);
    o.y = fpack2(v.z, v.w);
    ((uint2*)dst)[i] = o;
}

__global__ void pooled_kernel(const float* __restrict__ dh,
                              const int* __restrict__ cap,
                              uint16_t* __restrict__ ph)
{
    int b  = blockIdx.x;
    int d4 = threadIdx.x;
    float4 acc = make_float4(0.f, 0.f, 0.f, 0.f);
    float len = 0.f;
    #pragma unroll
    for (int t = 0; t < T_STEPS; t++) {
        int v = cap[t * B_SZ + b];
        float m = (v != 0 && v != 2) ? 1.f : 0.f;
        len += m;
        float4 x = *(const float4*)(dh + (size_t)t * B_SZ * D_SZ + (size_t)b * D_SZ + d4 * 4);
        acc.x += m * x.x; acc.y += m * x.y; acc.z += m * x.z; acc.w += m * x.w;
    }
    float inv = 1.f / len;
    uint2 o;
    o.x = fpack2(acc.x * inv, acc.y * inv);
    o.y = fpack2(acc.z * inv, acc.w * inv);
    ((uint2*)(ph + (size_t)b * D_SZ))[d4] = o;
}

// zero out[:,0,:]; reset grid-barrier counter
__global__ void init_kernel(float* __restrict__ out)
{
    int idx = blockIdx.x * blockDim.x + threadIdx.x;   // over B*H
    int b = idx >> 10;
    int j = idx & 1023;
    out[(size_t)b * T_STEPS * H_SZ + j] = 0.f;
    if (idx == 0) g_bar_ctr = 0u;
}

// ---------------------------------------------------------------------------
extern "C" void kernel_launch(void* const* d_in, const int* in_sizes, int n_in,
                              void* d_out, int out_size)
{
    const float* dh    = (const float*)d_in[0];      // [T,1,B,D] == [T,B,D]
    const int*   cap   = (const int*)d_in[2];        // [T,B] int32
    const float* W_ih  = (const float*)d_in[3];      // [4H, 2D]
    const float* W_hh  = (const float*)d_in[4];      // [4H, H]
    const float* b_ih  = (const float*)d_in[5];      // [4H]
    const float* b_hh  = (const float*)d_in[6];      // [4H]
    float*       out   = (float*)d_out;              // [B, T, H]

    float *Gpool, *Gin, *biasp;
    uint16_t *wih_h, *whh_h, *dh_h, *pl_h, *h_h;
    cudaGetSymbolAddress((void**)&Gpool, g_Gpool);
    cudaGetSymbolAddress((void**)&Gin,   g_Gin);
    cudaGetSymbolAddress((void**)&biasp, g_bias_p);
    cudaGetSymbolAddress((void**)&wih_h, g_wih_h);
    cudaGetSymbolAddress((void**)&whh_h, g_whh_h);
    cudaGetSymbolAddress((void**)&dh_h,  g_dh_h);
    cudaGetSymbolAddress((void**)&pl_h,  g_pl_h);
    cudaGetSymbolAddress((void**)&h_h,   g_h_h);

    cudaFuncSetAttribute(gemm_f16, cudaFuncAttributeMaxDynamicSharedMemorySize, SMEM_B);
    cudaFuncSetAttribute(lstm_persist, cudaFuncAttributeMaxDynamicSharedMemorySize, SMEM_B);

    // 0) prep: permute weights -> fp16, bias; convert dh[1:]; pooled mean
    permute_w_f16<<<G4, 256>>>(W_ih, wih_h, 2 * D_SZ);
    permute_w_f16<<<G4, 256>>>(W_hh, whh_h, H_SZ);
    permute_bias<<<G4 / 256, 256>>>(b_ih, b_hh, biasp);
    conv_dh<<<((T_STEPS - 1) * B_SZ * D_SZ / 4) / 256, 256>>>(
        dh + (size_t)B_SZ * D_SZ, dh_h);
    pooled_kernel<<<B_SZ, 256>>>(dh, cap, pl_h);
    init_kernel<<<(B_SZ * H_SZ) / 256, 256>>>(out);

    // 1) Gpool = pooled @ Wihp[:, D:]^T + bias_p
    gemm_f16<<<dim3(G4 / 128, B_SZ / 128), 256, SMEM_B>>>(
        pl_h, D_SZ, wih_h + D_SZ, 2 * D_SZ,
        nullptr, 0, biasp, Gpool, G4, D_SZ);

    // 2) Gin[t-1] = dh[t] @ Wihp[:, :D]^T + Gpool   (one big parallel GEMM)
    gemm_f16<<<dim3(G4 / 128, ((T_STEPS - 1) * B_SZ) / 128), 256, SMEM_B>>>(
        dh_h, D_SZ, wih_h, 2 * D_SZ,
        Gpool, B_SZ, nullptr, Gin, G4, D_SZ);

    // 3) entire recurrence in ONE persistent kernel (grid barrier between steps)
    lstm_persist<<<128, 512, SMEM_B>>>(whh_h, Gin, h_h, out);
}